// round 16
// baseline (speedup 1.0000x reference)
#include <cuda_runtime.h>
#include <cuda_fp16.h>
#include <math.h>
#include <stdint.h>

#define H    256
#define BSZ  256
#define TLEN 128
#define G4   1024
#define DIN  512
#define SKA  264
#define SKB  520

__device__ float  g_wx[(size_t)2 * TLEN * G4 * BSZ];   // [d][t][j][b]
__device__ float  g_out0[(size_t)BSZ * TLEN * 512];
__device__ float  g_h[2 * BSZ * H];
__device__ float  g_c[2 * BSZ * H];
__device__ __half g_whhf[2 * 16 * 64 * 256];
__device__ __half g_inpf[16 * 64 * 256];
__device__ __half g_outpf[32 * 16 * 256];
__device__ __half g_xpf[32 * 4 * 256];
__device__ __half g_wihf0[2 * 8 * 64 * 256];
__device__ __half g_wihf1[2 * 32 * 64 * 256];
__device__ __half g_xbf[(size_t)TLEN * 32 * 4096];

__device__ __forceinline__ float sigf(float x) { return 1.0f / (1.0f + __expf(-x)); }
__device__ __forceinline__ float tanha(float x) {
    float r; asm("tanh.approx.f32 %0, %1;" : "=f"(r) : "f"(x)); return r;
}

__device__ __forceinline__ void mma16816(float d[4], unsigned a0, unsigned a1, unsigned a2,
                                         unsigned a3, unsigned b0, unsigned b1) {
    asm volatile(
        "mma.sync.aligned.m16n8k16.row.col.f32.f16.f16.f32 "
        "{%0,%1,%2,%3},{%4,%5,%6,%7},{%8,%9},{%0,%1,%2,%3};"
        : "+f"(d[0]), "+f"(d[1]), "+f"(d[2]), "+f"(d[3])
        : "r"(a0), "r"(a1), "r"(a2), "r"(a3), "r"(b0), "r"(b1));
}

__device__ __forceinline__ uint32_t mapa_u32(uint32_t addr, uint32_t trank) {
    uint32_t r;
    asm("mapa.shared::cluster.u32 %0, %1, %2;" : "=r"(r) : "r"(addr), "r"(trank));
    return r;
}
__device__ __forceinline__ void stc_u16(uint32_t addr, __half v) {
    unsigned short u = *(unsigned short*)&v;
    asm volatile("st.shared::cluster.u16 [%0], %1;" :: "r"(addr), "h"(u) : "memory");
}
__device__ __forceinline__ uint32_t sh32(const void* p) {
    return (uint32_t)__cvta_generic_to_shared(p);
}
#define CLUSTER_SYNC() do { \
    asm volatile("barrier.cluster.arrive.aligned;" ::: "memory"); \
    asm volatile("barrier.cluster.wait.aligned;" ::: "memory"); \
} while (0)

// W[j][k] row-major -> A-frag-native: out[((kt*MT+mt)*32+lane)*8 + h]
__global__ void prepfrag(const float* __restrict__ W, __half* __restrict__ out,
                         int MT, int KT, int J)
{
    int idx = blockIdx.x * 256 + threadIdx.x;
    if (idx >= MT * KT * 256) return;
    int h = idx & 7, lane = (idx >> 3) & 31;
    int tile = idx >> 8;
    int mt = tile % MT, kt = tile / MT;
    int reg = h >> 1;
    int j = mt * 16 + (lane >> 2) + (reg & 1) * 8;
    int k = kt * 16 + (lane & 3) * 2 + (reg >> 1) * 8 + (h & 1);
    out[idx] = (j < J) ? __float2half(W[(size_t)j * (KT * 16) + k]) : __float2half(0.0f);
}

// X[b][t][K] fp32 -> B-frag fp16 stream
__global__ void conv_bfrag(const float* __restrict__ X, __half* __restrict__ out,
                           int KT, int Kfull)
{
    int widx = blockIdx.x * 256 + threadIdx.x;
    if (widx >= TLEN * KT * 2048) return;
    int which = widx & 1;
    int lane  = (widx >> 1) & 31;
    int nt    = (widx >> 6) & 31;
    int kt    = (widx >> 11) % KT;
    int t     = (widx >> 11) / KT;
    int k = kt * 16 + which * 8 + (lane & 3) * 2;
    int b = nt * 8 + (lane >> 2);
    const float* p = X + ((size_t)b * TLEN + t) * Kfull + k;
    ((__half2*)out)[widx] = __floats2half2_rn(p[0], p[1]);
}

// ---------------- HMMA wx GEMM: g_wx[d][t][j][b] ----------------
__global__ __launch_bounds__(512) void wx_hmma(const __half* __restrict__ xbf,
                                               const __half* __restrict__ wf, int KT)
{
    const int d  = blockIdx.z;
    const int jb = blockIdx.y * 128;
    const int t  = blockIdx.x;
    const int ts = d ? (TLEN - 1 - t) : t;
    const int tid = threadIdx.x;
    const int w = tid >> 5, lane = tid & 31;
    const int mt = w >> 1, nt0 = (w & 1) * 16;
    const int r = lane >> 2, c2 = (lane & 3) * 2;
    const int mtg = (jb >> 4) + mt;

    const uint4* wfa = (const uint4*)(wf + (size_t)d * KT * 64 * 256);
    const uint2* bfr = (const uint2*)xbf;

    float acc[16][4];
#pragma unroll
    for (int q = 0; q < 16; q++)
#pragma unroll
        for (int i = 0; i < 4; i++) acc[q][i] = 0.0f;

    for (int kt = 0; kt < KT; kt++) {
        uint4 af = wfa[((size_t)kt * 64 + mtg) * 32 + lane];
        const uint2* bb = bfr + ((size_t)(ts * KT + kt)) * 1024 + nt0 * 32 + lane;
#pragma unroll
        for (int q = 0; q < 16; q++) {
            uint2 bv = bb[q * 32];
            mma16816(acc[q], af.x, af.y, af.z, af.w, bv.x, bv.y);
        }
    }
    const int j = jb + mt * 16 + r;
    float* obase = g_wx + (((size_t)(d * TLEN + t)) * G4 + j) * BSZ;
#pragma unroll
    for (int q = 0; q < 16; q++) {
        int b = (nt0 + q) * 8 + c2;
        *(float2*)(obase + b)           = make_float2(acc[q][0], acc[q][1]);
        *(float2*)(obase + 8 * BSZ + b) = make_float2(acc[q][2], acc[q][3]);
    }
}

// ---------------- scan: 2-CTA cluster, M-split, N=16 ----------------
struct SS {
    __half hT[16 * SKA];
    __half uT[16 * SKA];
    __half xmT[16 * SKB];
    __half zsT[16 * SKB];
    __half yT[16 * SKB];
    __half dtw[DIN * 16];
    float  gates[3][16 * 256];
    float  cst[16 * 256];
    float  xdbl[16 * 64];
    float  epart[2][8][32][2][4];
    float  bsum[G4];
    float  cw1[DIN], cb[DIN], dm[DIN], dtb[DIN];
};

__global__ __launch_bounds__(1024) __cluster_dims__(2, 1, 1)
void scan_kernel(
    const __half* __restrict__ whhf,
    const float*  __restrict__ bih,
    const float*  __restrict__ bhh,
    const __half* __restrict__ inpf,
    const __half* __restrict__ outpf,
    const __half* __restrict__ xpf,
    const float*  __restrict__ conv_w,
    const float*  __restrict__ conv_b,
    const float*  __restrict__ dt_w,
    const float*  __restrict__ dt_b,
    const float*  __restrict__ Dm,
    float* __restrict__ outbuf,
    int first_layer)
{
    extern __shared__ char sraw[];
    SS* S = (SS*)sraw;
    const int tid  = threadIdx.x;
    const int w    = tid >> 5, lane = tid & 31;
    const int r    = lane >> 2, c2 = (lane & 3) * 2;
    const int nb   = lane >> 2;
    const int p    = blockIdx.x & 1;            // cluster rank
    const int pairid = blockIdx.x >> 1;         // 0..31
    const int dd   = pairid >> 4;
    const int b0g  = (pairid & 15) * 16;
    const uint4* whw = (const uint4*)(whhf + (size_t)dd * 16 * 64 * 256);

    const uint32_t lbase = sh32(S);
    const uint32_t dpeer = mapa_u32(lbase, (uint32_t)(p ^ 1)) - lbase;

    // ---- init ----
    S->bsum[tid] = bih[dd * G4 + tid] + bhh[dd * G4 + tid];
    if (tid < 512) {
        S->cw1[tid] = conv_w[tid * 2 + 1];
        S->cb[tid]  = conv_b[tid];
        S->dm[tid]  = Dm[tid];
        S->dtb[tid] = dt_b[tid];
    }
#pragma unroll
    for (int i = 0; i < 8; i++) S->dtw[tid + i * 1024] = __float2half(dt_w[tid + i * 1024]);
#pragma unroll
    for (int i = 0; i < 4; i++) {
        int idx = tid + i * 1024;               // 4096 = 16n x 256j
        int n = idx >> 8, j = idx & 255;
        if (first_layer) {
            S->hT[n * SKA + j] = __float2half(0.0f);
            S->cst[idx] = 0.0f;
        } else {
            S->hT[n * SKA + j] = __float2half(g_h[((size_t)dd * BSZ + b0g + n) * H + j]);
            S->cst[idx] = g_c[((size_t)dd * BSZ + b0g + n) * H + j];
        }
    }
    __syncthreads();
    CLUSTER_SYNC();

    const int mtg = (w >> 3) * 16 + p * 8 + (w & 7);   // A/B tile for this warp
    const int sA  = w >> 3;

    for (int t = 0; t < TLEN; t++) {
        // ---- A: g = wx + h @ Whh^T  (rank's 32 tiles, 1/warp, 2 n-tiles) ----
        float da[2][4];
        {
            const float* wxt = g_wx + ((size_t)(dd * TLEN + t)) * G4 * BSZ;
            int j = mtg * 16 + r;
            const float* pp = wxt + (size_t)j * BSZ + b0g + c2;
#pragma unroll
            for (int nt = 0; nt < 2; nt++) {
                float2 lo = *(const float2*)(pp + nt * 8);
                float2 hi = *(const float2*)(pp + nt * 8 + 8 * BSZ);
                da[nt][0] = lo.x; da[nt][1] = lo.y; da[nt][2] = hi.x; da[nt][3] = hi.y;
            }
        }
#pragma unroll 4
        for (int kt = 0; kt < 16; kt++) {
            uint4 f = whw[(kt * 64 + mtg) * 32 + lane];
#pragma unroll
            for (int nt = 0; nt < 2; nt++) {
                unsigned bb0 = *(const unsigned*)&S->hT[(nt * 8 + nb) * SKA + kt * 16 + c2];
                unsigned bb1 = *(const unsigned*)&S->hT[(nt * 8 + nb) * SKA + kt * 16 + c2 + 8];
                mma16816(da[nt], f.x, f.y, f.z, f.w, bb0, bb1);
            }
        }
        {
            int j = mtg * 16 + r;
            if (sA == 0) {
#pragma unroll
                for (int nt = 0; nt < 2; nt++)
#pragma unroll
                    for (int q = 0; q < 4; q++) {
                        int jj = j + (q >> 1) * 8, n = nt * 8 + c2 + (q & 1);
                        __half v = __float2half(da[nt][q]);
                        S->uT[n * SKA + jj] = v;
                        stc_u16(sh32(&S->uT[n * SKA + jj]) + dpeer, v);
                    }
            } else {
                int gi = sA - 1, jo = j & 255;
#pragma unroll
                for (int nt = 0; nt < 2; nt++)
#pragma unroll
                    for (int q = 0; q < 4; q++) {
                        int jj = jo + (q >> 1) * 8, n = nt * 8 + c2 + (q & 1);
                        S->gates[gi][n * 256 + jj] = da[nt][q];
                    }
            }
        }
        CLUSTER_SYNC();

        // ---- B: xz = u @ in_proj^T ----
#pragma unroll
        for (int nt = 0; nt < 2; nt++)
#pragma unroll
            for (int q = 0; q < 4; q++) da[nt][q] = 0.0f;
#pragma unroll 4
        for (int kt = 0; kt < 16; kt++) {
            uint4 f = ((const uint4*)inpf)[(kt * 64 + mtg) * 32 + lane];
#pragma unroll
            for (int nt = 0; nt < 2; nt++) {
                unsigned bb0 = *(const unsigned*)&S->uT[(nt * 8 + nb) * SKA + kt * 16 + c2];
                unsigned bb1 = *(const unsigned*)&S->uT[(nt * 8 + nb) * SKA + kt * 16 + c2 + 8];
                mma16816(da[nt], f.x, f.y, f.z, f.w, bb0, bb1);
            }
        }
        {
            int j = mtg * 16 + r;
            if (sA < 2) {        // xm: local + remote
#pragma unroll
                for (int nt = 0; nt < 2; nt++)
#pragma unroll
                    for (int q = 0; q < 4; q++) {
                        int jj = j + (q >> 1) * 8, n = nt * 8 + c2 + (q & 1);
                        float pre = da[nt][q] * S->cw1[jj] + S->cb[jj];
                        __half v = __float2half(pre * sigf(pre));
                        S->xmT[n * SKB + jj] = v;
                        stc_u16(sh32(&S->xmT[n * SKB + jj]) + dpeer, v);
                    }
            } else {             // zs: local only
                int jz = j - 512;
#pragma unroll
                for (int nt = 0; nt < 2; nt++)
#pragma unroll
                    for (int q = 0; q < 4; q++) {
                        int jj = jz + (q >> 1) * 8, n = nt * 8 + c2 + (q & 1);
                        float z = da[nt][q];
                        S->zsT[n * SKB + jj] = __float2half(z * sigf(z));
                    }
            }
        }
        CLUSTER_SYNC();

        // ---- C: x_dbl = xm @ x_proj^T (duplicated, warps 0-3, 2 n-tiles) ----
        if (w < 4) {
            float dc[2][4] = {{0, 0, 0, 0}, {0, 0, 0, 0}};
#pragma unroll 4
            for (int kt = 0; kt < 32; kt++) {
                uint4 f = ((const uint4*)xpf)[(kt * 4 + w) * 32 + lane];
#pragma unroll
                for (int nt = 0; nt < 2; nt++) {
                    unsigned bb0 = *(const unsigned*)&S->xmT[(nt * 8 + nb) * SKB + kt * 16 + c2];
                    unsigned bb1 = *(const unsigned*)&S->xmT[(nt * 8 + nb) * SKB + kt * 16 + c2 + 8];
                    mma16816(dc[nt], f.x, f.y, f.z, f.w, bb0, bb1);
                }
            }
            int o = w * 16 + r;
#pragma unroll
            for (int nt = 0; nt < 2; nt++)
#pragma unroll
                for (int q = 0; q < 4; q++) {
                    int oo = o + (q >> 1) * 8, n = nt * 8 + c2 + (q & 1);
                    S->xdbl[n * 64 + oo] = dc[nt][q];
                }
        }
        __syncthreads();

        // ---- D: (rank's 256 j) bcs inline, delta/softplus, y; 4 n per thread ----
        {
            int jl = tid & 255;
            int j  = (jl & 127) + ((jl >> 7) << 8) + p * 128;
            int nh = tid >> 8;                   // 0..3 -> 4 n each
            float wr[16];
#pragma unroll
            for (int q = 0; q < 16; q++) wr[q] = __half2float(S->dtw[j * 16 + q]);
            float dtbj = S->dtb[j], dmj = S->dm[j];
#pragma unroll
            for (int nn = 0; nn < 4; nn++) {
                int n = nh * 4 + nn;
                float bcs = 0.0f;
#pragma unroll
                for (int ss = 0; ss < 16; ss++)
                    bcs += S->xdbl[n * 64 + 16 + ss] * S->xdbl[n * 64 + 32 + ss];
                float s = dtbj;
#pragma unroll
                for (int rr = 0; rr < 16; rr++) s += S->xdbl[n * 64 + rr] * wr[rr];
                float delta = fmaxf(s, 0.0f) + __logf(1.0f + __expf(-fabsf(s)));
                float y = (delta * bcs + dmj) * __half2float(S->xmT[n * SKB + j])
                                              * __half2float(S->zsT[n * SKB + j]);
                __half v = __float2half(y);
                S->yT[n * SKB + j] = v;
                stc_u16(sh32(&S->yT[n * SKB + j]) + dpeer, v);
            }
        }
        CLUSTER_SYNC();

        // ---- E: mamba_out partials (warps 0-15: 8 tiles x 2-way K-split x 2 nt) ----
        if (w < 16) {
            int tile = w & 7, kh = w >> 3;
            int mt = p * 8 + tile;
            float de[2][4] = {{0, 0, 0, 0}, {0, 0, 0, 0}};
#pragma unroll 4
            for (int kk = 0; kk < 16; kk++) {
                int kt = kh * 16 + kk;
                uint4 f = ((const uint4*)outpf)[(kt * 16 + mt) * 32 + lane];
#pragma unroll
                for (int nt = 0; nt < 2; nt++) {
                    unsigned bb0 = *(const unsigned*)&S->yT[(nt * 8 + nb) * SKB + kt * 16 + c2];
                    unsigned bb1 = *(const unsigned*)&S->yT[(nt * 8 + nb) * SKB + kt * 16 + c2 + 8];
                    mma16816(de[nt], f.x, f.y, f.z, f.w, bb0, bb1);
                }
            }
#pragma unroll
            for (int nt = 0; nt < 2; nt++)
#pragma unroll
                for (int q = 0; q < 4; q++) S->epart[kh][tile][lane][nt][q] = de[nt][q];
        }
        __syncthreads();

        // ---- F: gates, state, output (warps 0-7: rank's j-half, 16 n) ----
        if (w < 8) {
            int tile = w;
            int mt = p * 8 + tile;
            int t_out = dd ? (TLEN - 1 - t) : t;
#pragma unroll
            for (int nt = 0; nt < 2; nt++)
#pragma unroll
                for (int q = 0; q < 4; q++) {
                    int jj = mt * 16 + r + (q >> 1) * 8;
                    int n  = nt * 8 + c2 + (q & 1);
                    int ix = n * 256 + jj;
                    float ipre = S->epart[0][tile][lane][nt][q] + S->epart[1][tile][lane][nt][q];
                    float iv = sigf(ipre + S->bsum[jj]);
                    float fv = sigf(S->gates[0][ix] + S->bsum[256 + jj]);
                    float gv = tanha(S->gates[1][ix] + S->bsum[512 + jj]);
                    float ov = sigf(S->gates[2][ix] + S->bsum[768 + jj]);
                    float cn = fv * S->cst[ix] + iv * gv;
                    float hn = ov * tanha(cn);
                    S->cst[ix] = cn;
                    __half hv = __float2half(hn);
                    S->hT[n * SKA + jj] = hv;
                    stc_u16(sh32(&S->hT[n * SKA + jj]) + dpeer, hv);
                    outbuf[((size_t)(b0g + n) * TLEN + t_out) * 512 + dd * 256 + jj] = hn;
                }
        }
        CLUSTER_SYNC();
    }

    // final states: rank stores its j-half for all 16 n
#pragma unroll
    for (int i = 0; i < 2; i++) {
        int idx = tid + i * 1024;               // 2048 = 16n x 128j
        int n = idx >> 7, jl = idx & 127;
        int j = p * 128 + jl;
        g_h[((size_t)dd * BSZ + b0g + n) * H + j] = __half2float(S->hT[n * SKA + j]);
        g_c[((size_t)dd * BSZ + b0g + n) * H + j] = S->cst[n * 256 + j];
    }
    CLUSTER_SYNC();
}

// =====================================================================
extern "C" void kernel_launch(void* const* d_in, const int* in_sizes, int n_in,
                              void* d_out, int out_size)
{
    (void)in_sizes; (void)n_in; (void)out_size;
    const float* x        = (const float*)d_in[0];
    const float* w_ih_l0  = (const float*)d_in[1];
    const float* w_hh_l0  = (const float*)d_in[2];
    const float* b_ih_l0  = (const float*)d_in[3];
    const float* b_hh_l0  = (const float*)d_in[4];
    const float* w_ih_l1  = (const float*)d_in[5];
    const float* w_hh_l1  = (const float*)d_in[6];
    const float* b_ih_l1  = (const float*)d_in[7];
    const float* b_hh_l1  = (const float*)d_in[8];
    const float* in_proj  = (const float*)d_in[9];
    const float* conv_w   = (const float*)d_in[10];
    const float* conv_b   = (const float*)d_in[11];
    const float* x_proj   = (const float*)d_in[12];
    const float* dt_w     = (const float*)d_in[13];
    const float* dt_b     = (const float*)d_in[14];
    const float* Dm       = (const float*)d_in[15];
    const float* out_proj = (const float*)d_in[16];
    float* out = (float*)d_out;

    static int inited = 0;
    int smem_bytes = (int)sizeof(SS);
    if (!inited) {
        cudaFuncSetAttribute(scan_kernel, cudaFuncAttributeMaxDynamicSharedMemorySize, smem_bytes);
        inited = 1;
    }

    float*  out0;   cudaGetSymbolAddress((void**)&out0,   g_out0);
    __half* whhf;   cudaGetSymbolAddress((void**)&whhf,   g_whhf);
    __half* inpf;   cudaGetSymbolAddress((void**)&inpf,   g_inpf);
    __half* outpf;  cudaGetSymbolAddress((void**)&outpf,  g_outpf);
    __half* xpf;    cudaGetSymbolAddress((void**)&xpf,    g_xpf);
    __half* wihf0;  cudaGetSymbolAddress((void**)&wihf0,  g_wihf0);
    __half* wihf1;  cudaGetSymbolAddress((void**)&wihf1,  g_wihf1);
    __half* xbf;    cudaGetSymbolAddress((void**)&xbf,    g_xbf);

    // layer-independent frag weights
    prepfrag<<<(16 * 64 * 256 + 255) / 256, 256>>>(in_proj, inpf, 64, 16, 1024);
    prepfrag<<<(32 * 16 * 256 + 255) / 256, 256>>>(out_proj, outpf, 16, 32, 256);
    prepfrag<<<(32 * 4 * 256 + 255) / 256, 256>>>(x_proj, xpf, 4, 32, 48);
    prepfrag<<<(8 * 64 * 256 + 255) / 256, 256>>>(w_ih_l0, wihf0, 64, 8, 1024);
    prepfrag<<<(8 * 64 * 256 + 255) / 256, 256>>>(w_ih_l0 + (size_t)G4 * 128,
                                                  wihf0 + 8 * 64 * 256, 64, 8, 1024);
    prepfrag<<<(32 * 64 * 256 + 255) / 256, 256>>>(w_ih_l1, wihf1, 64, 32, 1024);
    prepfrag<<<(32 * 64 * 256 + 255) / 256, 256>>>(w_ih_l1 + (size_t)G4 * 512,
                                                   wihf1 + 32 * 64 * 256, 64, 32, 1024);

    // ---- layer 0 ----
    prepfrag<<<(16 * 64 * 256 + 255) / 256, 256>>>(w_hh_l0, whhf, 64, 16, 1024);
    prepfrag<<<(16 * 64 * 256 + 255) / 256, 256>>>(w_hh_l0 + (size_t)G4 * H,
                                                   whhf + 16 * 64 * 256, 64, 16, 1024);
    conv_bfrag<<<(TLEN * 8 * 2048 + 255) / 256, 256>>>(x, xbf, 8, 128);
    wx_hmma<<<dim3(TLEN, 8, 2), 512>>>(xbf, wihf0, 8);
    scan_kernel<<<64, 1024, smem_bytes>>>(whhf, b_ih_l0, b_hh_l0, inpf, outpf, xpf,
        conv_w, conv_b, dt_w, dt_b, Dm, out0, 1);

    // ---- layer 1 ----
    prepfrag<<<(16 * 64 * 256 + 255) / 256, 256>>>(w_hh_l1, whhf, 64, 16, 1024);
    prepfrag<<<(16 * 64 * 256 + 255) / 256, 256>>>(w_hh_l1 + (size_t)G4 * H,
                                                   whhf + 16 * 64 * 256, 64, 16, 1024);
    conv_bfrag<<<(TLEN * 32 * 2048 + 255) / 256, 256>>>(out0, xbf, 32, 512);
    wx_hmma<<<dim3(TLEN, 8, 2), 512>>>(xbf, wihf1, 32);
    scan_kernel<<<64, 1024, smem_bytes>>>(whhf, b_ih_l1, b_hh_l1, inpf, outpf, xpf,
        conv_w, conv_b, dt_w, dt_b, Dm, out, 0);
}